// round 13
// baseline (speedup 1.0000x reference)
#include <cuda_runtime.h>
#include <cuda_fp16.h>
#include <cstdint>
#include <cstddef>

// Problem constants
#define N_NODES 50000
#define N_PAD   50048
#define KNBR    32
#define FDIM    128
#define EDIM    8
#define KDIM    1024          // FDIM * EDIM

#define BM        64
#define KC        32
#define NKCHUNKS  (KDIM / KC)             // 32
#define OFF_A     0
#define OFF_B     4096
#define BUF_BYTES 12288                   // 4K (A) + 8K (B)
#define NSTAGES   3
#define SMEM_DYN  (NSTAGES * BUF_BYTES)   // 36 KB
#define NBLOCKS_M ((N_NODES + BM - 1) / BM)   // 782
#define S1_BLOCKS (N_NODES / 8)               // 6250
#define GRID_TOTAL (S1_BLOCKS + NBLOCKS_M)    // 7032

// G as fp16, rows [i][kk], kk = n*128 + l  (zero-init; rows >= 50000 stay 0)
__device__ __half g_h[(size_t)N_PAD * KDIM];   // 102.5 MB
// W rearranged to [kk][m] fp16
__device__ __half wt_h[KDIM * FDIM];
// per-tile completion counters (each launch: +8 by producers, reset by consumer)
__device__ int g_cnt[NBLOCKS_M];

// ---------------------------------------------------------------------------
// helpers
// ---------------------------------------------------------------------------
__device__ __forceinline__ uint32_t smem_u32(const void* p) {
    uint32_t a;
    asm("{ .reg .u64 t; cvta.to.shared.u64 t, %1; cvt.u32.u64 %0, t; }" : "=r"(a) : "l"(p));
    return a;
}

__device__ __forceinline__ void cp_async16(uint32_t dst, const void* src) {
    asm volatile("cp.async.cg.shared.global [%0], [%1], 16;" :: "r"(dst), "l"(src));
}
__device__ __forceinline__ void cp_commit() {
    asm volatile("cp.async.commit_group;");
}

__device__ __forceinline__ void ldm_x4(uint32_t* r, uint32_t addr) {
    asm volatile("ldmatrix.sync.aligned.m8n8.x4.shared.b16 {%0,%1,%2,%3}, [%4];"
                 : "=r"(r[0]), "=r"(r[1]), "=r"(r[2]), "=r"(r[3]) : "r"(addr));
}
__device__ __forceinline__ void ldm_x4t(uint32_t* r, uint32_t addr) {
    asm volatile("ldmatrix.sync.aligned.m8n8.x4.trans.shared.b16 {%0,%1,%2,%3}, [%4];"
                 : "=r"(r[0]), "=r"(r[1]), "=r"(r[2]), "=r"(r[3]) : "r"(addr));
}

__device__ __forceinline__ void mma_f16(float* c, const uint32_t* a, const uint32_t* b) {
    asm volatile(
        "mma.sync.aligned.m16n8k16.row.col.f32.f16.f16.f32 "
        "{%0,%1,%2,%3}, {%4,%5,%6,%7}, {%8,%9}, {%0,%1,%2,%3};"
        : "+f"(c[0]), "+f"(c[1]), "+f"(c[2]), "+f"(c[3])
        : "r"(a[0]), "r"(a[1]), "r"(a[2]), "r"(a[3]), "r"(b[0]), "r"(b[1]));
}

__device__ __forceinline__ void fma4(float4& a, float s, const float4& x) {
    a.x = fmaf(s, x.x, a.x);
    a.y = fmaf(s, x.y, a.y);
    a.z = fmaf(s, x.z, a.z);
    a.w = fmaf(s, x.w, a.w);
}

// ---------------------------------------------------------------------------
// Kernel 0: w (F,F,E) -> wt_h [kk][m],  kk = n*128 + l
// ---------------------------------------------------------------------------
__global__ void transpose_w_kernel(const float* __restrict__ w) {
    int idx = blockIdx.x * blockDim.x + threadIdx.x;
    if (idx >= KDIM * FDIM) return;
    int kk = idx >> 7;          // n*128 + l
    int m  = idx & 127;
    int n  = kk >> 7;
    int l  = kk & 127;
    wt_h[idx] = __float2half_rn(w[(l * FDIM + m) * EDIM + n]);
}

// ---------------------------------------------------------------------------
// FUSED OVERLAP kernel: two block roles in one grid.
//   blocks [0, S1_BLOCKS):        producer — gather-contract 8 nodes,
//                                 signal tile counter (release).
//   blocks [S1_BLOCKS, GRID):     consumer — spin until own 64-row tile's
//                                 producers signalled, then fp16 tensor GEMM.
// Deadlock-free: blocks dispatch in index order, producers never block, and
// a machine full of spinning consumers implies all producers retired.
// ---------------------------------------------------------------------------
__global__ void __launch_bounds__(256, 3) mp_overlap_kernel(
    const float* __restrict__ nodes,
    const int* __restrict__ nlist,
    const float* __restrict__ edges,
    const float* __restrict__ inv_degree,
    float* __restrict__ out)
{
    extern __shared__ __align__(128) char smem[];
    const int tid  = threadIdx.x;
    const int lane = tid & 31;
    const int wid  = tid >> 5;

    if (blockIdx.x < S1_BLOCKS) {
        // ==================== PRODUCER: gather-contract ====================
        int*   s_nb = (int*)smem;                    // [8][32]
        float* s_e  = (float*)(smem + 1024);         // [8][256]
        const int i = blockIdx.x * 8 + wid;

        int nbi = nlist[(size_t)i * KNBR + lane];
        nbi = nbi < 0 ? 0 : (nbi >= N_NODES ? N_NODES - 1 : nbi);
        s_nb[wid * KNBR + lane] = nbi;

        const float4* e4 = (const float4*)(edges + (size_t)i * (KNBR * EDIM));
        float4* se4 = (float4*)(s_e + wid * (KNBR * EDIM));
        se4[lane * 2 + 0] = e4[lane * 2 + 0];
        se4[lane * 2 + 1] = e4[lane * 2 + 1];
        __syncwarp();

        float4 acc[EDIM];
#pragma unroll
        for (int n = 0; n < EDIM; n++) acc[n] = make_float4(0.f, 0.f, 0.f, 0.f);

        const float* ew = s_e + wid * (KNBR * EDIM);
        const int*   nw = s_nb + wid * KNBR;
#pragma unroll 4
        for (int j = 0; j < KNBR; j++) {
            const int nb = nw[j];
            const float4 x = *(const float4*)(nodes + (size_t)nb * FDIM + lane * 4);
            const float4 e0 = *(const float4*)&ew[j * 8 + 0];
            const float4 e1 = *(const float4*)&ew[j * 8 + 4];
            fma4(acc[0], e0.x, x);
            fma4(acc[1], e0.y, x);
            fma4(acc[2], e0.z, x);
            fma4(acc[3], e0.w, x);
            fma4(acc[4], e1.x, x);
            fma4(acc[5], e1.y, x);
            fma4(acc[6], e1.z, x);
            fma4(acc[7], e1.w, x);
        }

        const size_t rbase = (size_t)i * KDIM + lane * 4;
#pragma unroll
        for (int n = 0; n < EDIM; n++) {
            __half2 a = __floats2half2_rn(acc[n].x, acc[n].y);
            __half2 b = __floats2half2_rn(acc[n].z, acc[n].w);
            *(uint2*)&g_h[rbase + n * FDIM] = make_uint2(*(uint32_t*)&a, *(uint32_t*)&b);
        }

        // signal: all 8 rows of this CTA live in tile blockIdx.x>>3
        __syncthreads();
        __threadfence();
        if (tid == 0) atomicAdd(&g_cnt[blockIdx.x >> 3], 1);
        return;
    }

    // ====================== CONSUMER: tensor GEMM ==========================
    const int tile = blockIdx.x - S1_BLOCKS;
    const int m0   = tile * BM;

    if (tid == 0) {
        const int thr = (tile == NBLOCKS_M - 1) ? 2 : 8;   // last tile: 2 CTAs
        while (atomicAdd(&g_cnt[tile], 0) < thr) __nanosleep(200);
    }
    __syncthreads();
    __threadfence();

    const uint32_t sbase = smem_u32(smem);
    const int warp_m = wid & 3;        // m offset 16*warp_m
    const int warp_n = wid >> 2;       // n offset 64*warp_n

    float acc[8][4];
#pragma unroll
    for (int nt = 0; nt < 8; nt++)
#pragma unroll
        for (int q = 0; q < 4; q++) acc[nt][q] = 0.f;

    auto load_chunk = [&](int kc, int b) {
        if (kc < NKCHUNKS) {
            const uint32_t sb = sbase + b * BUF_BYTES;
            // A: 64 rows x 32 cols fp16 = 256 x 16B chunks (1 per thread)
            {
                const int row = tid >> 2;
                const int c   = tid & 3;
                const uint32_t so = row * 64 + ((c ^ ((row >> 1) & 3)) << 4);
                const size_t ge = (size_t)(m0 + row) * KDIM + kc * KC + c * 8;
                cp_async16(sb + OFF_A + so, g_h + ge);
            }
            // B: 32 rows x 128 cols fp16 = 512 x 16B chunks (2 per thread)
#pragma unroll
            for (int it = 0; it < 2; it++) {
                const int cb  = tid + it * 256;
                const int row = cb >> 4;
                const int c   = cb & 15;
                const uint32_t so = row * 256 + ((c ^ (row & 15)) << 4);
                const size_t ge = (size_t)(kc * KC + row) * FDIM + c * 8;
                cp_async16(sb + OFF_B + so, wt_h + ge);
            }
        }
        cp_commit();
    };

    load_chunk(0, 0);
    load_chunk(1, 1);

#pragma unroll 1
    for (int kc = 0; kc < NKCHUNKS; kc++) {
        asm volatile("cp.async.wait_group 1;");
        __syncthreads();

        load_chunk(kc + 2, (kc + 2) % NSTAGES);

        const uint32_t sb = sbase + (kc % NSTAGES) * BUF_BYTES;

#pragma unroll
        for (int k16 = 0; k16 < 2; k16++) {
            uint32_t af[4];
            const int rA  = (lane & 7) + ((lane >> 3) & 1) * 8;
            const int kch = k16 * 2 + (lane >> 4);
            {
                const int row = warp_m * 16 + rA;
                const uint32_t off = row * 64 + ((kch ^ ((row >> 1) & 3)) << 4);
                ldm_x4(af, sb + OFF_A + off);
            }
            const int rB = k16 * 16 + (lane & 7) + ((lane >> 3) & 1) * 8;
#pragma unroll
            for (int nt16 = 0; nt16 < 4; nt16++) {
                const int nch = warp_n * 8 + nt16 * 2 + (lane >> 4);
                const uint32_t off = rB * 256 + ((nch ^ (rB & 15)) << 4);
                uint32_t bf[4];
                ldm_x4t(bf, sb + OFF_B + off);
                mma_f16(acc[nt16 * 2 + 0], af, bf + 0);
                mma_f16(acc[nt16 * 2 + 1], af, bf + 2);
            }
        }
    }

    // ---- epilogue: scale + store ----
    {
        const int r0 = m0 + warp_m * 16 + (lane >> 2);
        const int r1 = r0 + 8;
        const float s0 = (r0 < N_NODES) ? inv_degree[r0] : 0.f;
        const float s1 = (r1 < N_NODES) ? inv_degree[r1] : 0.f;
#pragma unroll
        for (int nt = 0; nt < 8; nt++) {
            const int col = warp_n * 64 + nt * 8 + (lane & 3) * 2;
            if (r0 < N_NODES) {
                float2 o = make_float2(acc[nt][0] * s0, acc[nt][1] * s0);
                *(float2*)(out + (size_t)r0 * FDIM + col) = o;
            }
            if (r1 < N_NODES) {
                float2 o = make_float2(acc[nt][2] * s1, acc[nt][3] * s1);
                *(float2*)(out + (size_t)r1 * FDIM + col) = o;
            }
        }
    }

    // reset counter for the next (graph-replayed) launch
    if (tid == 0) atomicExch(&g_cnt[tile], 0);
}

// ---------------------------------------------------------------------------
// Launch. Inputs identified BY ELEMENT COUNT (all five distinct).
// ---------------------------------------------------------------------------
extern "C" void kernel_launch(void* const* d_in, const int* in_sizes, int n_in,
                              void* d_out, int out_size) {
    const float* nodes      = nullptr;
    const int*   nlist      = nullptr;
    const float* edges      = nullptr;
    const float* inv_degree = nullptr;
    const float* w          = nullptr;

    for (int i = 0; i < n_in; i++) {
        switch (in_sizes[i]) {
            case 6400000:  nodes      = (const float*)d_in[i]; break;
            case 1600000:  nlist      = (const int*)d_in[i];   break;
            case 12800000: edges      = (const float*)d_in[i]; break;
            case 50000:    inv_degree = (const float*)d_in[i]; break;
            case 131072:   w          = (const float*)d_in[i]; break;
            default: break;
        }
    }
    if (!nodes || !nlist || !edges || !inv_degree || !w) return;

    float* out = (float*)d_out;

    cudaFuncSetAttribute(mp_overlap_kernel,
                         cudaFuncAttributeMaxDynamicSharedMemorySize, SMEM_DYN);

    transpose_w_kernel<<<(KDIM * FDIM + 255) / 256, 256>>>(w);
    mp_overlap_kernel<<<GRID_TOTAL, 256, SMEM_DYN>>>(
        nodes, nlist, edges, inv_degree, out);
}

// round 14
// speedup vs baseline: 1.1664x; 1.1664x over previous
#include <cuda_runtime.h>
#include <cuda_fp16.h>
#include <cstdint>
#include <cstddef>

// Problem constants
#define N_NODES 50000
#define N_PAD   50048
#define KNBR    32
#define FDIM    128
#define EDIM    8
#define KDIM    1024          // FDIM * EDIM

// G as fp16, rows [i][kk], kk = n*128 + l  (zero-init; rows >= 50000 stay 0)
__device__ __half g_h[(size_t)N_PAD * KDIM];   // 102.5 MB
// W rearranged to [kk][m] fp16
__device__ __half wt_h[KDIM * FDIM];
// fp16 copy of nodes (gather table)
__device__ __half nodes_h[(size_t)N_NODES * FDIM];   // 12.8 MB

// ---------------------------------------------------------------------------
// helpers
// ---------------------------------------------------------------------------
__device__ __forceinline__ uint32_t smem_u32(const void* p) {
    uint32_t a;
    asm("{ .reg .u64 t; cvta.to.shared.u64 t, %1; cvt.u32.u64 %0, t; }" : "=r"(a) : "l"(p));
    return a;
}

__device__ __forceinline__ void cp_async16(uint32_t dst, const void* src) {
    asm volatile("cp.async.cg.shared.global [%0], [%1], 16;" :: "r"(dst), "l"(src));
}
__device__ __forceinline__ void cp_commit() {
    asm volatile("cp.async.commit_group;");
}

__device__ __forceinline__ void ldm_x4(uint32_t* r, uint32_t addr) {
    asm volatile("ldmatrix.sync.aligned.m8n8.x4.shared.b16 {%0,%1,%2,%3}, [%4];"
                 : "=r"(r[0]), "=r"(r[1]), "=r"(r[2]), "=r"(r[3]) : "r"(addr));
}
__device__ __forceinline__ void ldm_x4t(uint32_t* r, uint32_t addr) {
    asm volatile("ldmatrix.sync.aligned.m8n8.x4.trans.shared.b16 {%0,%1,%2,%3}, [%4];"
                 : "=r"(r[0]), "=r"(r[1]), "=r"(r[2]), "=r"(r[3]) : "r"(addr));
}

__device__ __forceinline__ void mma_f16(float* c, const uint32_t* a, const uint32_t* b) {
    asm volatile(
        "mma.sync.aligned.m16n8k16.row.col.f32.f16.f16.f32 "
        "{%0,%1,%2,%3}, {%4,%5,%6,%7}, {%8,%9}, {%0,%1,%2,%3};"
        : "+f"(c[0]), "+f"(c[1]), "+f"(c[2]), "+f"(c[3])
        : "r"(a[0]), "r"(a[1]), "r"(a[2]), "r"(a[3]), "r"(b[0]), "r"(b[1]));
}

// ---------------------------------------------------------------------------
// Kernel 0a: w (F,F,E) -> wt_h [kk][m],  kk = n*128 + l
// ---------------------------------------------------------------------------
__global__ void transpose_w_kernel(const float* __restrict__ w) {
    int idx = blockIdx.x * blockDim.x + threadIdx.x;
    if (idx >= KDIM * FDIM) return;
    int kk = idx >> 7;          // n*128 + l
    int m  = idx & 127;
    int n  = kk >> 7;
    int l  = kk & 127;
    wt_h[idx] = __float2half_rn(w[(l * FDIM + m) * EDIM + n]);
}

// ---------------------------------------------------------------------------
// Kernel 0b: nodes fp32 -> fp16 table
// ---------------------------------------------------------------------------
__global__ void convert_nodes_kernel(const float* __restrict__ nodes) {
    int idx = blockIdx.x * blockDim.x + threadIdx.x;   // 4 elements each
    if (idx * 4 >= N_NODES * FDIM) return;
    const float4 v = *(const float4*)(nodes + idx * 4);
    __half2 a = __floats2half2_rn(v.x, v.y);
    __half2 b = __floats2half2_rn(v.z, v.w);
    *(uint2*)&nodes_h[(size_t)idx * 4] = make_uint2(*(uint32_t*)&a, *(uint32_t*)&b);
}

// ---------------------------------------------------------------------------
// Kernel 1: stage 1 on TENSOR CORES. One warp per node i.
//   D[l, e] = sum_j X[j, l] * E[j, e]   (M=128, N=8, K=32)
// X gathered fp16 into per-warp swizzled smem; A frags via ldmatrix.trans
// (source is X[j,l] = A^T, same trans pattern as stage2's proven B path);
// E frags via ldmatrix.trans on 32x8 fp16 edges tile.
// ---------------------------------------------------------------------------
#define S1_WSTRIDE 8960                       // 8KB X + 512B E + 128B nb + pad (256B-aligned)
#define S1_SMEM    (8 * S1_WSTRIDE)           // 70 KB

__global__ void __launch_bounds__(256, 2) stage1_tensor_kernel(
    const int* __restrict__ nlist,
    const float* __restrict__ edges)
{
    extern __shared__ __align__(256) char smem[];
    const int tid  = threadIdx.x;
    const int lane = tid & 31;
    const int wid  = tid >> 5;
    const int i    = blockIdx.x * 8 + wid;    // grid 6250 -> 50000 nodes

    char* wb = smem + wid * S1_WSTRIDE;
    const uint32_t xb  = smem_u32(wb);        // X tile: 32 rows x 256B (swizzled)
    const uint32_t ebs = xb + 8192;           // E tile: 32 rows x 16B
    int* nbp = (int*)(wb + 8704);             // 32 ints

    // neighbor indices (int32, proven) + clamp
    int nb = nlist[(size_t)i * KNBR + lane];
    nb = nb < 0 ? 0 : (nb >= N_NODES ? N_NODES - 1 : nb);
    nbp[lane] = nb;

    // edges row: lane loads j-row (8 fp32), converts, stores 16B to E tile
    {
        const float4* e4 = (const float4*)(edges + (size_t)i * (KNBR * EDIM));
        const float4 a = e4[lane * 2 + 0];
        const float4 b = e4[lane * 2 + 1];
        __half2 h0 = __floats2half2_rn(a.x, a.y);
        __half2 h1 = __floats2half2_rn(a.z, a.w);
        __half2 h2 = __floats2half2_rn(b.x, b.y);
        __half2 h3 = __floats2half2_rn(b.z, b.w);
        *(uint4*)(wb + 8192 + lane * 16) =
            make_uint4(*(uint32_t*)&h0, *(uint32_t*)&h1, *(uint32_t*)&h2, *(uint32_t*)&h3);
    }
    __syncwarp();

    // gather X: 32 rows x 256B fp16, swizzle chunk' = c ^ (row & 15)
#pragma unroll
    for (int it = 0; it < 16; it++) {
        const int jrow = it * 2 + (lane >> 4);
        const int c    = lane & 15;
        const uint32_t dst = xb + jrow * 256 + ((c ^ (jrow & 15)) << 4);
        cp_async16(dst, nodes_h + (size_t)nbp[jrow] * FDIM + c * 8);
    }
    cp_commit();
    asm volatile("cp.async.wait_group 0;");
    __syncwarp();

    // E fragments: b-frags for k(=j) 0-15 -> ebf[0,1], k 16-31 -> ebf[2,3]
    uint32_t ebf[4];
    ldm_x4t(ebf, ebs + lane * 16);

    float acc[8][4];
#pragma unroll
    for (int mt = 0; mt < 8; mt++)
#pragma unroll
        for (int q = 0; q < 4; q++) acc[mt][q] = 0.f;

    // A-frag lane mapping (trans): krow by bits {0-2, 4}, m-col-8 by bit 3
    const int krow_lo = (lane & 7) + ((lane >> 4) & 1) * 8;
    const int mc8     = (lane >> 3) & 1;

#pragma unroll
    for (int mt = 0; mt < 8; mt++) {
        const int ch = mt * 2 + mc8;          // 16B chunk within X row
        uint32_t a0[4], a1[4];
        {
            const int kr = krow_lo;           // k 0-15
            ldm_x4t(a0, xb + kr * 256 + ((ch ^ (kr & 15)) << 4));
        }
        {
            const int kr = krow_lo + 16;      // k 16-31
            ldm_x4t(a1, xb + kr * 256 + ((ch ^ (kr & 15)) << 4));
        }
        mma_f16(acc[mt], a0, ebf + 0);
        mma_f16(acc[mt], a1, ebf + 2);
    }

    // store G fp16: D[l, e] -> g_h[i*1024 + e*128 + l]
    const size_t gb = (size_t)i * KDIM;
    const int e0 = (lane & 3) * 2;
#pragma unroll
    for (int mt = 0; mt < 8; mt++) {
        const int l0 = mt * 16 + (lane >> 2);
        g_h[gb + e0 * FDIM + l0]           = __float2half_rn(acc[mt][0]);
        g_h[gb + (e0 + 1) * FDIM + l0]     = __float2half_rn(acc[mt][1]);
        g_h[gb + e0 * FDIM + l0 + 8]       = __float2half_rn(acc[mt][2]);
        g_h[gb + (e0 + 1) * FDIM + l0 + 8] = __float2half_rn(acc[mt][3]);
    }
}

// ---------------------------------------------------------------------------
// Kernel 2: mma.sync fp16 GEMM (unchanged from best-known R12).
// BM=64 x BN=128, 4-stage cp.async, 3 CTAs/SM, reversed tile order.
// ---------------------------------------------------------------------------
#define BM        64
#define KC        32
#define NKCHUNKS  (KDIM / KC)         // 32
#define OFF_A     0
#define OFF_B     4096
#define BUF_BYTES 12288               // 4K (A) + 8K (B)
#define NSTAGES   4
#define SMEM_DYN  (NSTAGES * BUF_BYTES)   // 48 KB
#define NBLOCKS_M ((N_NODES + BM - 1) / BM)   // 782

__global__ void __launch_bounds__(256, 3) stage2_mma_kernel(
    const float* __restrict__ inv_degree,
    float* __restrict__ out)
{
    extern __shared__ __align__(128) char smem[];
    const uint32_t sbase = smem_u32(smem);

    const int tid    = threadIdx.x;
    const int lane   = tid & 31;
    const int wid    = tid >> 5;
    const int warp_m = wid & 3;
    const int warp_n = wid >> 2;
    const int m0     = (NBLOCKS_M - 1 - blockIdx.x) * BM;

    float acc[8][4];
#pragma unroll
    for (int nt = 0; nt < 8; nt++)
#pragma unroll
        for (int q = 0; q < 4; q++) acc[nt][q] = 0.f;

    auto load_chunk = [&](int kc, int b) {
        if (kc < NKCHUNKS) {
            const uint32_t sb = sbase + b * BUF_BYTES;
            {
                const int row = tid >> 2;
                const int c   = tid & 3;
                const uint32_t so = row * 64 + ((c ^ ((row >> 1) & 3)) << 4);
                const size_t ge = (size_t)(m0 + row) * KDIM + kc * KC + c * 8;
                cp_async16(sb + OFF_A + so, g_h + ge);
            }
#pragma unroll
            for (int it = 0; it < 2; it++) {
                const int cb  = tid + it * 256;
                const int row = cb >> 4;
                const int c   = cb & 15;
                const uint32_t so = row * 256 + ((c ^ (row & 15)) << 4);
                const size_t ge = (size_t)(kc * KC + row) * FDIM + c * 8;
                cp_async16(sb + OFF_B + so, wt_h + ge);
            }
        }
        cp_commit();
    };

    load_chunk(0, 0);
    load_chunk(1, 1);
    load_chunk(2, 2);

#pragma unroll 1
    for (int kc = 0; kc < NKCHUNKS; kc++) {
        asm volatile("cp.async.wait_group 2;");
        __syncthreads();

        load_chunk(kc + 3, (kc + 3) % NSTAGES);

        const uint32_t sb = sbase + (kc % NSTAGES) * BUF_BYTES;

#pragma unroll
        for (int k16 = 0; k16 < 2; k16++) {
            uint32_t af[4];
            const int rA  = (lane & 7) + ((lane >> 3) & 1) * 8;
            const int kch = k16 * 2 + (lane >> 4);
            {
                const int row = warp_m * 16 + rA;
                const uint32_t off = row * 64 + ((kch ^ ((row >> 1) & 3)) << 4);
                ldm_x4(af, sb + OFF_A + off);
            }
            const int rB = k16 * 16 + (lane & 7) + ((lane >> 3) & 1) * 8;
#pragma unroll
            for (int nt16 = 0; nt16 < 4; nt16++) {
                const int nch = warp_n * 8 + nt16 * 2 + (lane >> 4);
                const uint32_t off = rB * 256 + ((nch ^ (rB & 15)) << 4);
                uint32_t bf[4];
                ldm_x4t(bf, sb + OFF_B + off);
                mma_f16(acc[nt16 * 2 + 0], af, bf + 0);
                mma_f16(acc[nt16 * 2 + 1], af, bf + 2);
            }
        }
    }

    {
        const int r0 = m0 + warp_m * 16 + (lane >> 2);
        const int r1 = r0 + 8;
        const float s0 = (r0 < N_NODES) ? inv_degree[r0] : 0.f;
        const float s1 = (r1 < N_NODES) ? inv_degree[r1] : 0.f;
#pragma unroll
        for (int nt = 0; nt < 8; nt++) {
            const int col = warp_n * 64 + nt * 8 + (lane & 3) * 2;
            if (r0 < N_NODES) {
                float2 o = make_float2(acc[nt][0] * s0, acc[nt][1] * s0);
                *(float2*)(out + (size_t)r0 * FDIM + col) = o;
            }
            if (r1 < N_NODES) {
                float2 o = make_float2(acc[nt][2] * s1, acc[nt][3] * s1);
                *(float2*)(out + (size_t)r1 * FDIM + col) = o;
            }
        }
    }
}

// ---------------------------------------------------------------------------
// Launch. Inputs identified BY ELEMENT COUNT (all five distinct).
// ---------------------------------------------------------------------------
extern "C" void kernel_launch(void* const* d_in, const int* in_sizes, int n_in,
                              void* d_out, int out_size) {
    const float* nodes      = nullptr;
    const int*   nlist      = nullptr;
    const float* edges      = nullptr;
    const float* inv_degree = nullptr;
    const float* w          = nullptr;

    for (int i = 0; i < n_in; i++) {
        switch (in_sizes[i]) {
            case 6400000:  nodes      = (const float*)d_in[i]; break;
            case 1600000:  nlist      = (const int*)d_in[i];   break;
            case 12800000: edges      = (const float*)d_in[i]; break;
            case 50000:    inv_degree = (const float*)d_in[i]; break;
            case 131072:   w          = (const float*)d_in[i]; break;
            default: break;
        }
    }
    if (!nodes || !nlist || !edges || !inv_degree || !w) return;

    float* out = (float*)d_out;

    cudaFuncSetAttribute(stage1_tensor_kernel,
                         cudaFuncAttributeMaxDynamicSharedMemorySize, S1_SMEM);
    cudaFuncSetAttribute(stage2_mma_kernel,
                         cudaFuncAttributeMaxDynamicSharedMemorySize, SMEM_DYN);

    transpose_w_kernel<<<(KDIM * FDIM + 255) / 256, 256>>>(w);
    convert_nodes_kernel<<<(N_NODES * FDIM / 4 + 255) / 256, 256>>>(nodes);
    stage1_tensor_kernel<<<N_NODES / 8, 256, S1_SMEM>>>(nlist, edges);
    stage2_mma_kernel<<<NBLOCKS_M, 256, SMEM_DYN>>>(inv_degree, out);
}